// round 7
// baseline (speedup 1.0000x reference)
#include <cuda_runtime.h>
#include <cuda_bf16.h>
#include <cstdint>

#define D_MODEL 256
#define NB 16
#define ACT_OFF 10
#define LN_EPS 1e-5f
#define THREADS 128
#define WARPS 4
#define TPB 128
#define GTOK 4
#define CAP (1 << 19)

// ---- persistent scratch (allocation-free rule: __device__ globals) ----
__device__ float  g_CT[128 * D_MODEL];   // combined actor+street+type table, 128 KB
__device__ float  g_G[NB * NB];          // Gram = W W^T
__device__ float  g_c[NB];               // W b
__device__ float  g_S[NB];               // row sums of W
__device__ float  g_k2[2];               // {sum(b), sum(b^2)}
__device__ float2 g_stats[CAP];          // per-token (mu, rs)
__device__ int    g_cidx[CAP];           // packed combo index, -1 if inactive

// ================= prep: combined table + Gram constants =================
__global__ __launch_bounds__(256)
void prep_kernel(const float* __restrict__ actor_emb,
                 const float* __restrict__ street_emb,
                 const float* __restrict__ type_emb,
                 const float* __restrict__ mlp_w,
                 const float* __restrict__ mlp_b)
{
    if (blockIdx.x < 128) {
        const int combo = blockIdx.x;
        const int a = combo >> 6, s = (combo >> 4) & 3, k = combo & 15;
        const int d = threadIdx.x;
        g_CT[combo * D_MODEL + d] = __ldg(actor_emb  + a * D_MODEL + d)
                                  + __ldg(street_emb + s * D_MODEL + d)
                                  + __ldg(type_emb   + k * D_MODEL + d);
    } else {
        __shared__ float Wsh[NB * D_MODEL];
        __shared__ float bsh[D_MODEL];
        for (int i = threadIdx.x; i < NB * D_MODEL / 4; i += 256)
            reinterpret_cast<float4*>(Wsh)[i] = __ldg(reinterpret_cast<const float4*>(mlp_w) + i);
        bsh[threadIdx.x] = __ldg(mlp_b + threadIdx.x);
        __syncthreads();

        const int kl = threadIdx.x;          // 0..255
        const int k = kl >> 4, l = kl & 15;
        float g = 0.f;
        for (int d = 0; d < D_MODEL; d++)
            g = fmaf(Wsh[k * D_MODEL + d], Wsh[l * D_MODEL + d], g);
        g_G[kl] = g;
        if (kl < NB) {
            float c = 0.f, S = 0.f;
            for (int d = 0; d < D_MODEL; d++) {
                c = fmaf(Wsh[kl * D_MODEL + d], bsh[d], c);
                S += Wsh[kl * D_MODEL + d];
            }
            g_c[kl] = c; g_S[kl] = S;
        }
        if (kl == 255) {
            float Sb = 0.f, Sbb = 0.f;
            for (int d = 0; d < D_MODEL; d++) { Sb += bsh[d]; Sbb = fmaf(bsh[d], bsh[d], Sbb); }
            g_k2[0] = Sb; g_k2[1] = Sbb;
        }
    }
}

// ================= per-token LN stats via Gram quadratic form =================
__global__ __launch_bounds__(256)
void stats_kernel(const int* __restrict__ token_ids,
                  const int* __restrict__ action_actors,
                  const int* __restrict__ action_streets,
                  const float* __restrict__ legal_masks,
                  int n_tok)
{
    const int t = blockIdx.x * 256 + threadIdx.x;
    if (t >= n_tok) return;
    const int tk = __ldg(token_ids + t);
    if (tk < ACT_OFF || tk >= ACT_OFF + NB) { g_cidx[t] = -1; return; }

    int a = __ldg(action_actors  + t); a = a < 0 ? 0 : (a > 1 ? 1 : a);
    int s = __ldg(action_streets + t); s = s < 0 ? 0 : (s > 3 ? 3 : s);
    g_cidx[t] = (((a << 2) | s) << 4) | (tk - ACT_OFF);

    float m[NB];
    const float4* lm = reinterpret_cast<const float4*>(legal_masks + (size_t)t * NB);
    #pragma unroll
    for (int i = 0; i < 4; i++) {
        float4 v = __ldg(lm + i);
        m[4*i+0] = v.x; m[4*i+1] = v.y; m[4*i+2] = v.z; m[4*i+3] = v.w;
    }

    float sum = __ldg(&g_k2[0]);
    float qs  = __ldg(&g_k2[1]);
    #pragma unroll
    for (int k = 0; k < NB; k++) sum = fmaf(m[k], __ldg(g_S + k), sum);
    #pragma unroll
    for (int k = 0; k < NB; k++) {
        float r = 2.0f * __ldg(g_c + k);
        #pragma unroll
        for (int l = 0; l < NB; l++)
            r = fmaf(__ldg(g_G + k * NB + l), m[l], r);
        qs = fmaf(m[k], r, qs);
    }
    const float inv = 1.0f / 256.0f;
    const float mu  = sum * inv;
    const float var = fmaf(qs, inv, -mu * mu);
    g_stats[t] = make_float2(mu, rsqrtf(var + LN_EPS));
}

// ================= main kernel =================
__global__ __launch_bounds__(THREADS, 4)
void action_embedding_kernel(
    const float* __restrict__ legal_masks,
    const float* __restrict__ mlp_w,
    const float* __restrict__ mlp_b,
    const float* __restrict__ ln_gamma,
    const float* __restrict__ ln_beta,
    float*       __restrict__ out,
    int n_tok)
{
    __shared__ float Wsh[NB * D_MODEL];
    __shared__ unsigned short alist[TPB];
    __shared__ unsigned short ilist[TPB];
    __shared__ int cnts[2];

    const int tid  = threadIdx.x;
    const int warp = tid >> 5;
    const int lane = tid & 31;
    const int d0   = 4 * lane;
    const int base = blockIdx.x * TPB;

    #pragma unroll
    for (int i = tid; i < NB * D_MODEL / 4; i += THREADS)
        reinterpret_cast<float4*>(Wsh)[i] = __ldg(reinterpret_cast<const float4*>(mlp_w) + i);
    if (tid < 2) cnts[tid] = 0;
    __syncthreads();

    // classify + compact from g_cidx
    {
        const int t = base + tid;
        const bool valid = (t < n_tok);
        const bool act = valid && (__ldg(g_cidx + t) >= 0);
        const unsigned am = __ballot_sync(0xFFFFFFFFu, act);
        const unsigned im = __ballot_sync(0xFFFFFFFFu, valid && !act);
        int ab = 0, ib = 0;
        if (lane == 0) {
            ab = atomicAdd(&cnts[0], __popc(am));
            ib = atomicAdd(&cnts[1], __popc(im));
        }
        ab = __shfl_sync(0xFFFFFFFFu, ab, 0);
        ib = __shfl_sync(0xFFFFFFFFu, ib, 0);
        const unsigned lt = (1u << lane) - 1u;
        if (act)        alist[ab + __popc(am & lt)] = (unsigned short)tid;
        else if (valid) ilist[ib + __popc(im & lt)] = (unsigned short)tid;
    }
    __syncthreads();
    const int n_act = cnts[0];
    const int n_in  = cnts[1];

    // zero-fill inactive
    {
        const float4 z = make_float4(0.f, 0.f, 0.f, 0.f);
        for (int i = warp; i < n_in; i += WARPS) {
            float4* dst = reinterpret_cast<float4*>(out + (size_t)(base + ilist[i]) * D_MODEL);
            dst[lane]      = z;
            dst[lane + 32] = z;
        }
    }

    // active: GTOK tokens per warp iteration
    for (int g = warp * GTOK; g < n_act; g += WARPS * GTOK) {
        const int cnt = min(GTOK, n_act - g);

        int tt[GTOK];
        #pragma unroll
        for (int j = 0; j < GTOK; j++)
            tt[j] = base + alist[g + (j < cnt ? j : 0)];

        // prefetch per-token stats + combo index (uniform loads)
        float2 st[GTOK];
        int    ci[GTOK];
        #pragma unroll
        for (int j = 0; j < GTOK; j++) {
            st[j] = __ldg(&g_stats[tt[j]]);
            ci[j] = __ldg(&g_cidx[tt[j]]);
        }

        float4 acc0[GTOK], acc1[GTOK];
        {
            const float4 b0 = __ldg(reinterpret_cast<const float4*>(mlp_b + d0));
            const float4 b1 = __ldg(reinterpret_cast<const float4*>(mlp_b + 128 + d0));
            #pragma unroll
            for (int j = 0; j < GTOK; j++) { acc0[j] = b0; acc1[j] = b1; }
        }

        #pragma unroll
        for (int kc = 0; kc < 4; kc++) {
            float4 m4[GTOK];
            #pragma unroll
            for (int j = 0; j < GTOK; j++)
                m4[j] = __ldg(reinterpret_cast<const float4*>(legal_masks + (size_t)tt[j] * NB) + kc);
            #pragma unroll
            for (int kk = 0; kk < 4; kk++) {
                const int k = kc * 4 + kk;
                const float4 w0 = *reinterpret_cast<const float4*>(&Wsh[k * D_MODEL + d0]);
                const float4 w1 = *reinterpret_cast<const float4*>(&Wsh[k * D_MODEL + 128 + d0]);
                #pragma unroll
                for (int j = 0; j < GTOK; j++) {
                    const float mk = (&m4[j].x)[kk];
                    acc0[j].x = fmaf(mk, w0.x, acc0[j].x);
                    acc0[j].y = fmaf(mk, w0.y, acc0[j].y);
                    acc0[j].z = fmaf(mk, w0.z, acc0[j].z);
                    acc0[j].w = fmaf(mk, w0.w, acc0[j].w);
                    acc1[j].x = fmaf(mk, w1.x, acc1[j].x);
                    acc1[j].y = fmaf(mk, w1.y, acc1[j].y);
                    acc1[j].z = fmaf(mk, w1.z, acc1[j].z);
                    acc1[j].w = fmaf(mk, w1.w, acc1[j].w);
                }
            }
        }

        // epilogue: no reductions — stats precomputed
        #pragma unroll
        for (int j = 0; j < GTOK; j++) {
            if (j >= cnt) break;     // warp-uniform
            const float mu = st[j].x;
            const float rs = st[j].y;
            const float* ct = g_CT + ci[j] * D_MODEL;
            float4* dst = reinterpret_cast<float4*>(out + (size_t)tt[j] * D_MODEL);
            #pragma unroll
            for (int c = 0; c < 2; c++) {
                const int dd = c * 128 + d0;
                const float4 acc = c ? acc1[j] : acc0[j];
                const float4 ga = __ldg(reinterpret_cast<const float4*>(ln_gamma + dd));
                const float4 be = __ldg(reinterpret_cast<const float4*>(ln_beta  + dd));
                const float4 e  = __ldg(reinterpret_cast<const float4*>(ct + dd));
                float4 r;
                r.x = fmaxf(fmaf((acc.x - mu) * rs, ga.x, be.x), 0.f) + e.x;
                r.y = fmaxf(fmaf((acc.y - mu) * rs, ga.y, be.y), 0.f) + e.y;
                r.z = fmaxf(fmaf((acc.z - mu) * rs, ga.z, be.z), 0.f) + e.z;
                r.w = fmaxf(fmaf((acc.w - mu) * rs, ga.w, be.w), 0.f) + e.w;
                dst[lane + 32 * c] = r;
            }
        }
    }
}

extern "C" void kernel_launch(void* const* d_in, const int* in_sizes, int n_in,
                              void* d_out, int out_size)
{
    const int*   token_ids   = (const int*)  d_in[0];
    const int*   actors      = (const int*)  d_in[1];
    const int*   streets     = (const int*)  d_in[2];
    const float* legal_masks = (const float*)d_in[3];
    const float* actor_emb   = (const float*)d_in[4];
    const float* street_emb  = (const float*)d_in[5];
    const float* type_emb    = (const float*)d_in[6];
    const float* mlp_w       = (const float*)d_in[7];
    const float* mlp_b       = (const float*)d_in[8];
    const float* ln_gamma    = (const float*)d_in[9];
    const float* ln_beta     = (const float*)d_in[10];
    float* out = (float*)d_out;

    const int n_tok = in_sizes[0];

    prep_kernel<<<129, 256>>>(actor_emb, street_emb, type_emb, mlp_w, mlp_b);
    stats_kernel<<<(n_tok + 255) / 256, 256>>>(token_ids, actors, streets, legal_masks, n_tok);
    const int blocks = (n_tok + TPB - 1) / TPB;
    action_embedding_kernel<<<blocks, THREADS>>>(
        legal_masks, mlp_w, mlp_b, ln_gamma, ln_beta, out, n_tok);
}

// round 9
// speedup vs baseline: 1.1447x; 1.1447x over previous
#include <cuda_runtime.h>
#include <cuda_bf16.h>
#include <cstdint>

#define D_MODEL 256
#define NB 16
#define ACT_OFF 10
#define LN_EPS 1e-5f
#define THREADS 128
#define WARPS 4
#define TPB 128
#define GTOK 4
#define CAP (1 << 19)

// ---- persistent scratch (__device__ globals; no allocation) ----
__device__ float  g_CT[128 * D_MODEL];   // combined actor+street+type table
__device__ float  g_G[NB * NB];          // Gram = W W^T
__device__ float  g_c[NB];               // W b
__device__ float  g_S[NB];               // row sums of W
__device__ float  g_k2[2];               // {sum(b), sum(b^2)}
__device__ float4 g_pack[CAP];           // per-token (mu, rs, combo_as_float, unused)
__device__ int    g_cidx[CAP];           // combo index, -1 if inactive

// ================= prep: combined table + Gram constants (parallel) =================
__global__ __launch_bounds__(256)
void prep_kernel(const float* __restrict__ actor_emb,
                 const float* __restrict__ street_emb,
                 const float* __restrict__ type_emb,
                 const float* __restrict__ mlp_w,
                 const float* __restrict__ mlp_b)
{
    if (blockIdx.x < 128) {
        const int combo = blockIdx.x;
        const int a = combo >> 6, s = (combo >> 4) & 3, k = combo & 15;
        const int d = threadIdx.x;
        g_CT[combo * D_MODEL + d] = __ldg(actor_emb  + a * D_MODEL + d)
                                  + __ldg(street_emb + s * D_MODEL + d)
                                  + __ldg(type_emb   + k * D_MODEL + d);
        return;
    }
    // Gram blocks: warp-per-pair. blocks 128..159, 8 warps each -> 256 pairs
    const int warp = threadIdx.x >> 5;
    const int lane = threadIdx.x & 31;
    const int p = (blockIdx.x - 128) * 8 + warp;     // 0..255
    const int k = p >> 4, l = p & 15;
    const int d0 = 4 * lane;

    const float4 wk0 = __ldg(reinterpret_cast<const float4*>(mlp_w + k * D_MODEL + d0));
    const float4 wk1 = __ldg(reinterpret_cast<const float4*>(mlp_w + k * D_MODEL + 128 + d0));
    const float4 wl0 = __ldg(reinterpret_cast<const float4*>(mlp_w + l * D_MODEL + d0));
    const float4 wl1 = __ldg(reinterpret_cast<const float4*>(mlp_w + l * D_MODEL + 128 + d0));

    float g = wk0.x * wl0.x + wk0.y * wl0.y + wk0.z * wl0.z + wk0.w * wl0.w
            + wk1.x * wl1.x + wk1.y * wl1.y + wk1.z * wl1.z + wk1.w * wl1.w;
    #pragma unroll
    for (int o = 16; o > 0; o >>= 1) g += __shfl_xor_sync(0xFFFFFFFFu, g, o);
    if (lane == 0) g_G[p] = g;

    // For p < 16: k = 0, l = p, so ROW p IS wl (this was the round-8 bug: used wk)
    if (p < NB) {
        const float4 b0 = __ldg(reinterpret_cast<const float4*>(mlp_b + d0));
        const float4 b1 = __ldg(reinterpret_cast<const float4*>(mlp_b + 128 + d0));
        float c = wl0.x * b0.x + wl0.y * b0.y + wl0.z * b0.z + wl0.w * b0.w
                + wl1.x * b1.x + wl1.y * b1.y + wl1.z * b1.z + wl1.w * b1.w;
        float S = wl0.x + wl0.y + wl0.z + wl0.w + wl1.x + wl1.y + wl1.z + wl1.w;
        #pragma unroll
        for (int o = 16; o > 0; o >>= 1) {
            c += __shfl_xor_sync(0xFFFFFFFFu, c, o);
            S += __shfl_xor_sync(0xFFFFFFFFu, S, o);
        }
        if (lane == 0) { g_c[p] = c; g_S[p] = S; }
        if (p == 0) {
            float Sb  = b0.x + b0.y + b0.z + b0.w + b1.x + b1.y + b1.z + b1.w;
            float Sbb = b0.x*b0.x + b0.y*b0.y + b0.z*b0.z + b0.w*b0.w
                      + b1.x*b1.x + b1.y*b1.y + b1.z*b1.z + b1.w*b1.w;
            #pragma unroll
            for (int o = 16; o > 0; o >>= 1) {
                Sb  += __shfl_xor_sync(0xFFFFFFFFu, Sb,  o);
                Sbb += __shfl_xor_sync(0xFFFFFFFFu, Sbb, o);
            }
            if (lane == 0) { g_k2[0] = Sb; g_k2[1] = Sbb; }
        }
    }
}

// ================= per-token LN stats via Gram quadratic form =================
__global__ __launch_bounds__(256)
void stats_kernel(const int* __restrict__ token_ids,
                  const int* __restrict__ action_actors,
                  const int* __restrict__ action_streets,
                  const float* __restrict__ legal_masks,
                  int n_tok)
{
    const int t = blockIdx.x * 256 + threadIdx.x;
    if (t >= n_tok) return;
    const int tk = __ldg(token_ids + t);
    if (tk < ACT_OFF || tk >= ACT_OFF + NB) { g_cidx[t] = -1; return; }

    int a = __ldg(action_actors  + t); a = a < 0 ? 0 : (a > 1 ? 1 : a);
    int s = __ldg(action_streets + t); s = s < 0 ? 0 : (s > 3 ? 3 : s);
    const int combo = (((a << 2) | s) << 4) | (tk - ACT_OFF);
    g_cidx[t] = combo;

    float m[NB];
    const float4* lm = reinterpret_cast<const float4*>(legal_masks + (size_t)t * NB);
    #pragma unroll
    for (int i = 0; i < 4; i++) {
        float4 v = __ldg(lm + i);
        m[4*i+0] = v.x; m[4*i+1] = v.y; m[4*i+2] = v.z; m[4*i+3] = v.w;
    }

    float sum = __ldg(&g_k2[0]);
    float qs  = __ldg(&g_k2[1]);
    #pragma unroll
    for (int k = 0; k < NB; k++) sum = fmaf(m[k], __ldg(g_S + k), sum);
    #pragma unroll
    for (int k = 0; k < NB; k++) {
        float r = 2.0f * __ldg(g_c + k);
        #pragma unroll
        for (int l = 0; l < NB; l++)
            r = fmaf(__ldg(g_G + k * NB + l), m[l], r);
        qs = fmaf(m[k], r, qs);
    }
    const float inv = 1.0f / 256.0f;
    const float mu  = sum * inv;
    const float var = fmaf(qs, inv, -mu * mu);
    g_pack[t] = make_float4(mu, rsqrtf(var + LN_EPS), __int_as_float(combo), 0.f);
}

// ================= main kernel =================
__global__ __launch_bounds__(THREADS, 4)
void action_embedding_kernel(
    const float* __restrict__ legal_masks,
    const float* __restrict__ mlp_w,
    const float* __restrict__ mlp_b,
    const float* __restrict__ ln_gamma,
    const float* __restrict__ ln_beta,
    float*       __restrict__ out,
    int n_tok)
{
    __shared__ float Wsh[NB * D_MODEL];
    __shared__ unsigned short alist[TPB];
    __shared__ unsigned short ilist[TPB];
    __shared__ int cnts[2];

    const int tid  = threadIdx.x;
    const int warp = tid >> 5;
    const int lane = tid & 31;
    const int d0   = 4 * lane;
    const int base = blockIdx.x * TPB;

    #pragma unroll
    for (int i = tid; i < NB * D_MODEL / 4; i += THREADS)
        reinterpret_cast<float4*>(Wsh)[i] = __ldg(reinterpret_cast<const float4*>(mlp_w) + i);
    if (tid < 2) cnts[tid] = 0;
    __syncthreads();

    // classify + compact from g_cidx
    {
        const int t = base + tid;
        const bool valid = (t < n_tok);
        const bool act = valid && (__ldg(g_cidx + t) >= 0);
        const unsigned am = __ballot_sync(0xFFFFFFFFu, act);
        const unsigned im = __ballot_sync(0xFFFFFFFFu, valid && !act);
        int ab = 0, ib = 0;
        if (lane == 0) {
            ab = atomicAdd(&cnts[0], __popc(am));
            ib = atomicAdd(&cnts[1], __popc(im));
        }
        ab = __shfl_sync(0xFFFFFFFFu, ab, 0);
        ib = __shfl_sync(0xFFFFFFFFu, ib, 0);
        const unsigned lt = (1u << lane) - 1u;
        if (act)        alist[ab + __popc(am & lt)] = (unsigned short)tid;
        else if (valid) ilist[ib + __popc(im & lt)] = (unsigned short)tid;
    }
    __syncthreads();
    const int n_act = cnts[0];
    const int n_in  = cnts[1];

    // zero-fill inactive
    {
        const float4 z = make_float4(0.f, 0.f, 0.f, 0.f);
        for (int i = warp; i < n_in; i += WARPS) {
            float4* dst = reinterpret_cast<float4*>(out + (size_t)(base + ilist[i]) * D_MODEL);
            dst[lane]      = z;
            dst[lane + 32] = z;
        }
    }

    // active: GTOK tokens per warp iteration
    for (int g = warp * GTOK; g < n_act; g += WARPS * GTOK) {
        const int cnt = min(GTOK, n_act - g);

        int tt[GTOK];
        #pragma unroll
        for (int j = 0; j < GTOK; j++)
            tt[j] = base + alist[g + (j < cnt ? j : 0)];

        // one packed uniform load per token: (mu, rs, combo)
        float4 pk[GTOK];
        #pragma unroll
        for (int j = 0; j < GTOK; j++)
            pk[j] = __ldg(&g_pack[tt[j]]);

        float4 acc0[GTOK], acc1[GTOK];
        {
            const float4 b0 = __ldg(reinterpret_cast<const float4*>(mlp_b + d0));
            const float4 b1 = __ldg(reinterpret_cast<const float4*>(mlp_b + 128 + d0));
            #pragma unroll
            for (int j = 0; j < GTOK; j++) { acc0[j] = b0; acc1[j] = b1; }
        }

        #pragma unroll
        for (int kc = 0; kc < 4; kc++) {
            float4 m4[GTOK];
            #pragma unroll
            for (int j = 0; j < GTOK; j++)
                m4[j] = __ldg(reinterpret_cast<const float4*>(legal_masks + (size_t)tt[j] * NB) + kc);
            #pragma unroll
            for (int kk = 0; kk < 4; kk++) {
                const int k = kc * 4 + kk;
                const float4 w0 = *reinterpret_cast<const float4*>(&Wsh[k * D_MODEL + d0]);
                const float4 w1 = *reinterpret_cast<const float4*>(&Wsh[k * D_MODEL + 128 + d0]);
                #pragma unroll
                for (int j = 0; j < GTOK; j++) {
                    const float mk = (&m4[j].x)[kk];
                    acc0[j].x = fmaf(mk, w0.x, acc0[j].x);
                    acc0[j].y = fmaf(mk, w0.y, acc0[j].y);
                    acc0[j].z = fmaf(mk, w0.z, acc0[j].z);
                    acc0[j].w = fmaf(mk, w0.w, acc0[j].w);
                    acc1[j].x = fmaf(mk, w1.x, acc1[j].x);
                    acc1[j].y = fmaf(mk, w1.y, acc1[j].y);
                    acc1[j].z = fmaf(mk, w1.z, acc1[j].z);
                    acc1[j].w = fmaf(mk, w1.w, acc1[j].w);
                }
            }
        }

        // epilogue: stats precomputed, single fused table gather
        #pragma unroll
        for (int j = 0; j < GTOK; j++) {
            if (j >= cnt) break;     // warp-uniform
            const float mu = pk[j].x;
            const float rs = pk[j].y;
            const float* ct = g_CT + __float_as_int(pk[j].z) * D_MODEL;
            float4* dst = reinterpret_cast<float4*>(out + (size_t)tt[j] * D_MODEL);
            #pragma unroll
            for (int c = 0; c < 2; c++) {
                const int dd = c * 128 + d0;
                const float4 acc = c ? acc1[j] : acc0[j];
                const float4 ga = __ldg(reinterpret_cast<const float4*>(ln_gamma + dd));
                const float4 be = __ldg(reinterpret_cast<const float4*>(ln_beta  + dd));
                const float4 e  = __ldg(reinterpret_cast<const float4*>(ct + dd));
                float4 r;
                r.x = fmaxf(fmaf((acc.x - mu) * rs, ga.x, be.x), 0.f) + e.x;
                r.y = fmaxf(fmaf((acc.y - mu) * rs, ga.y, be.y), 0.f) + e.y;
                r.z = fmaxf(fmaf((acc.z - mu) * rs, ga.z, be.z), 0.f) + e.z;
                r.w = fmaxf(fmaf((acc.w - mu) * rs, ga.w, be.w), 0.f) + e.w;
                dst[lane + 32 * c] = r;
            }
        }
    }
}

extern "C" void kernel_launch(void* const* d_in, const int* in_sizes, int n_in,
                              void* d_out, int out_size)
{
    const int*   token_ids   = (const int*)  d_in[0];
    const int*   actors      = (const int*)  d_in[1];
    const int*   streets     = (const int*)  d_in[2];
    const float* legal_masks = (const float*)d_in[3];
    const float* actor_emb   = (const float*)d_in[4];
    const float* street_emb  = (const float*)d_in[5];
    const float* type_emb    = (const float*)d_in[6];
    const float* mlp_w       = (const float*)d_in[7];
    const float* mlp_b       = (const float*)d_in[8];
    const float* ln_gamma    = (const float*)d_in[9];
    const float* ln_beta     = (const float*)d_in[10];
    float* out = (float*)d_out;

    const int n_tok = in_sizes[0];

    prep_kernel<<<160, 256>>>(actor_emb, street_emb, type_emb, mlp_w, mlp_b);
    stats_kernel<<<(n_tok + 255) / 256, 256>>>(token_ids, actors, streets, legal_masks, n_tok);
    const int blocks = (n_tok + TPB - 1) / TPB;
    action_embedding_kernel<<<blocks, THREADS>>>(
        legal_masks, mlp_w, mlp_b, ln_gamma, ln_beta, out, n_tok);
}

// round 11
// speedup vs baseline: 1.4122x; 1.2337x over previous
#include <cuda_runtime.h>
#include <cuda_bf16.h>
#include <cstdint>

#define D_MODEL 256
#define NB 16
#define ACT_OFF 10
#define LN_EPS 1e-5f
#define THREADS 128
#define WARPS 4
#define TPB 128
#define GTOK 4

typedef unsigned long long u64;

__device__ __forceinline__ u64 pack2(float lo, float hi) {
    u64 r;
    asm("mov.b64 %0, {%1, %2};" : "=l"(r)
        : "r"(__float_as_uint(lo)), "r"(__float_as_uint(hi)));
    return r;
}
__device__ __forceinline__ u64 pack2s(float v) { return pack2(v, v); }
__device__ __forceinline__ u64 fma2(u64 a, u64 b, u64 c) {
    u64 r;
    asm("fma.rn.f32x2 %0, %1, %2, %3;" : "=l"(r) : "l"(a), "l"(b), "l"(c));
    return r;
}
__device__ __forceinline__ float2 unpack2(u64 v) {
    unsigned lo, hi;
    asm("mov.b64 {%0, %1}, %2;" : "=r"(lo), "=r"(hi) : "l"(v));
    return make_float2(__uint_as_float(lo), __uint_as_float(hi));
}

__global__ __launch_bounds__(THREADS, 4)
void action_embedding_kernel(
    const int*   __restrict__ token_ids,
    const int*   __restrict__ action_actors,
    const int*   __restrict__ action_streets,
    const float* __restrict__ legal_masks,
    const float* __restrict__ actor_emb,
    const float* __restrict__ street_emb,
    const float* __restrict__ type_emb,
    const float* __restrict__ mlp_w,
    const float* __restrict__ mlp_b,
    const float* __restrict__ ln_gamma,
    const float* __restrict__ ln_beta,
    float*       __restrict__ out,
    int n_tok)
{
    __shared__ float Wsh[NB * D_MODEL];        // 16 KB
    __shared__ unsigned short alist[TPB];
    __shared__ unsigned short ilist[TPB];
    __shared__ int cnts[2];

    const int tid  = threadIdx.x;
    const int warp = tid >> 5;
    const int lane = tid & 31;
    const int d0   = 4 * lane;
    const int base = blockIdx.x * TPB;

    // ---- stage W into shared ----
    #pragma unroll
    for (int i = tid; i < NB * D_MODEL / 4; i += THREADS)
        reinterpret_cast<float4*>(Wsh)[i] = __ldg(reinterpret_cast<const float4*>(mlp_w) + i);
    if (tid < 2) cnts[tid] = 0;
    __syncthreads();

    // ---- classify + compact (1 thread = 1 token) ----
    {
        const int t = base + tid;
        const bool valid = (t < n_tok);
        int tk = 0;
        if (valid) tk = __ldg(token_ids + t);
        const bool act = valid && (tk >= ACT_OFF) && (tk < ACT_OFF + NB);
        const unsigned am = __ballot_sync(0xFFFFFFFFu, act);
        const unsigned im = __ballot_sync(0xFFFFFFFFu, valid && !act);
        int ab = 0, ib = 0;
        if (lane == 0) {
            ab = atomicAdd(&cnts[0], __popc(am));
            ib = atomicAdd(&cnts[1], __popc(im));
        }
        ab = __shfl_sync(0xFFFFFFFFu, ab, 0);
        ib = __shfl_sync(0xFFFFFFFFu, ib, 0);
        const unsigned lt = (1u << lane) - 1u;
        if (act)        alist[ab + __popc(am & lt)] = (unsigned short)tid;
        else if (valid) ilist[ib + __popc(im & lt)] = (unsigned short)tid;
    }
    __syncthreads();
    const int n_act = cnts[0];
    const int n_in  = cnts[1];

    // ---- zero-fill inactive tokens: one warp per token ----
    {
        const float4 z = make_float4(0.f, 0.f, 0.f, 0.f);
        for (int i = warp; i < n_in; i += WARPS) {
            float4* dst = reinterpret_cast<float4*>(out + (size_t)(base + ilist[i]) * D_MODEL);
            dst[lane]      = z;
            dst[lane + 32] = z;
        }
    }

    // ---- persistent packed bias ----
    u64 bb[4];
    {
        const float4 b0 = __ldg(reinterpret_cast<const float4*>(mlp_b + d0));
        const float4 b1 = __ldg(reinterpret_cast<const float4*>(mlp_b + 128 + d0));
        bb[0] = pack2(b0.x, b0.y); bb[1] = pack2(b0.z, b0.w);
        bb[2] = pack2(b1.x, b1.y); bb[3] = pack2(b1.z, b1.w);
    }

    // ---- active tokens, GTOK per warp iteration ----
    for (int g = warp * GTOK; g < n_act; g += WARPS * GTOK) {
        const int cnt = min(GTOK, n_act - g);

        int tt[GTOK];
        #pragma unroll
        for (int j = 0; j < GTOK; j++)
            tt[j] = base + alist[g + (j < cnt ? j : 0)];

        // accumulators as f32x2 pairs: [0]=d0,d0+1 [1]=d0+2,d0+3 [2]=+128.. [3]=+130..
        u64 acc[GTOK][4];
        #pragma unroll
        for (int j = 0; j < GTOK; j++) {
            acc[j][0] = bb[0]; acc[j][1] = bb[1]; acc[j][2] = bb[2]; acc[j][3] = bb[3];
        }

        // GEMM: packed FFMA2, W from smem reused x GTOK
        #pragma unroll
        for (int kc = 0; kc < 4; kc++) {
            float4 m4[GTOK];
            #pragma unroll
            for (int j = 0; j < GTOK; j++)
                m4[j] = __ldg(reinterpret_cast<const float4*>(legal_masks + (size_t)tt[j] * NB) + kc);
            #pragma unroll
            for (int kk = 0; kk < 4; kk++) {
                const int k = kc * 4 + kk;
                const float4 w0 = *reinterpret_cast<const float4*>(&Wsh[k * D_MODEL + d0]);
                const float4 w1 = *reinterpret_cast<const float4*>(&Wsh[k * D_MODEL + 128 + d0]);
                const u64 wp0 = pack2(w0.x, w0.y), wp1 = pack2(w0.z, w0.w);
                const u64 wp2 = pack2(w1.x, w1.y), wp3 = pack2(w1.z, w1.w);
                #pragma unroll
                for (int j = 0; j < GTOK; j++) {
                    const u64 mm = pack2s((&m4[j].x)[kk]);
                    acc[j][0] = fma2(mm, wp0, acc[j][0]);
                    acc[j][1] = fma2(mm, wp1, acc[j][1]);
                    acc[j][2] = fma2(mm, wp2, acc[j][2]);
                    acc[j][3] = fma2(mm, wp3, acc[j][3]);
                }
            }
        }

        // unpack h, LN stats with interleaved butterflies
        float2 h[GTOK][4];
        float sm[GTOK], sq[GTOK];
        #pragma unroll
        for (int j = 0; j < GTOK; j++) {
            #pragma unroll
            for (int q = 0; q < 4; q++) h[j][q] = unpack2(acc[j][q]);
            sm[j] = (h[j][0].x + h[j][0].y) + (h[j][1].x + h[j][1].y)
                  + (h[j][2].x + h[j][2].y) + (h[j][3].x + h[j][3].y);
            sq[j] = fmaf(h[j][0].x, h[j][0].x, fmaf(h[j][0].y, h[j][0].y,
                    fmaf(h[j][1].x, h[j][1].x, fmaf(h[j][1].y, h[j][1].y,
                    fmaf(h[j][2].x, h[j][2].x, fmaf(h[j][2].y, h[j][2].y,
                    fmaf(h[j][3].x, h[j][3].x, h[j][3].y * h[j][3].y)))))));
        }
        #pragma unroll
        for (int o = 16; o > 0; o >>= 1) {
            #pragma unroll
            for (int j = 0; j < GTOK; j++) {
                sm[j] += __shfl_xor_sync(0xFFFFFFFFu, sm[j], o);
                sq[j] += __shfl_xor_sync(0xFFFFFFFFu, sq[j], o);
            }
        }

        // epilogue per token, channel-half at a time (short live ranges)
        #pragma unroll
        for (int j = 0; j < GTOK; j++) {
            if (j >= cnt) break;     // warp-uniform
            const float inv = 1.0f / 256.0f;
            const float mu  = sm[j] * inv;
            const float var = fmaf(sq[j], inv, -mu * mu);
            const float rs  = rsqrtf(var + LN_EPS);

            const int tkj = __ldg(token_ids + tt[j]);
            int a = __ldg(action_actors  + tt[j]); a = a < 0 ? 0 : (a > 1 ? 1 : a);
            int s = __ldg(action_streets + tt[j]); s = s < 0 ? 0 : (s > 3 ? 3 : s);
            const int aid = tkj - ACT_OFF;

            float4* dst = reinterpret_cast<float4*>(out + (size_t)tt[j] * D_MODEL);
            #pragma unroll
            for (int c = 0; c < 2; c++) {
                const int dd = c * 128 + d0;
                const float hx = h[j][2*c].x,  hy = h[j][2*c].y;
                const float hz = h[j][2*c+1].x, hw = h[j][2*c+1].y;
                const float4 ga = __ldg(reinterpret_cast<const float4*>(ln_gamma + dd));
                const float4 be = __ldg(reinterpret_cast<const float4*>(ln_beta  + dd));
                const float4 ea = __ldg(reinterpret_cast<const float4*>(actor_emb  + a   * D_MODEL + dd));
                const float4 es = __ldg(reinterpret_cast<const float4*>(street_emb + s   * D_MODEL + dd));
                const float4 et = __ldg(reinterpret_cast<const float4*>(type_emb   + aid * D_MODEL + dd));
                float4 r;
                r.x = fmaxf(fmaf((hx - mu) * rs, ga.x, be.x), 0.f) + ea.x + es.x + et.x;
                r.y = fmaxf(fmaf((hy - mu) * rs, ga.y, be.y), 0.f) + ea.y + es.y + et.y;
                r.z = fmaxf(fmaf((hz - mu) * rs, ga.z, be.z), 0.f) + ea.z + es.z + et.z;
                r.w = fmaxf(fmaf((hw - mu) * rs, ga.w, be.w), 0.f) + ea.w + es.w + et.w;
                dst[lane + 32 * c] = r;
            }
        }
    }
}

extern "C" void kernel_launch(void* const* d_in, const int* in_sizes, int n_in,
                              void* d_out, int out_size)
{
    const int*   token_ids   = (const int*)  d_in[0];
    const int*   actors      = (const int*)  d_in[1];
    const int*   streets     = (const int*)  d_in[2];
    const float* legal_masks = (const float*)d_in[3];
    const float* actor_emb   = (const float*)d_in[4];
    const float* street_emb  = (const float*)d_in[5];
    const float* type_emb    = (const float*)d_in[6];
    const float* mlp_w       = (const float*)d_in[7];
    const float* mlp_b       = (const float*)d_in[8];
    const float* ln_gamma    = (const float*)d_in[9];
    const float* ln_beta     = (const float*)d_in[10];
    float* out = (float*)d_out;

    const int n_tok  = in_sizes[0];
    const int blocks = (n_tok + TPB - 1) / TPB;
    action_embedding_kernel<<<blocks, THREADS>>>(
        token_ids, actors, streets, legal_masks,
        actor_emb, street_emb, type_emb,
        mlp_w, mlp_b, ln_gamma, ln_beta,
        out, n_tok);
}